// round 1
// baseline (speedup 1.0000x reference)
#include <cuda_runtime.h>

// NeighborsValuesAssigner: x(32,3,64,64), patches(2048,3,5,5), values(2048,128)
// out(32,128,64,64) fp32.
// dist[b,n,h,w] = 0.5*||p_n||^2 - <p_n, window(x,b,h,w)>; top-8 smallest per
// position; out = mean of values[idx] over the 8 neighbors.

#define BB 32
#define CC 3
#define HW 64
#define NN 2048
#define DD 128
#define KNN 8
#define KVOL 75          // 3*5*5
#define NP 128           // patches per smem chunk
#define NCHUNK (NN / NP) // 16
#define NPOS (BB * HW * HW) // 131072

__device__ float g_bias[NN];
__device__ int g_topk[NPOS * KNN];

// ---------------------------------------------------------------------------
// Kernel 1: bias_n = 0.5 * sum(p^2)
// ---------------------------------------------------------------------------
__global__ void bias_kernel(const float* __restrict__ patches) {
    int n = blockIdx.x * blockDim.x + threadIdx.x;
    if (n < NN) {
        const float* p = patches + n * KVOL;
        float s = 0.f;
#pragma unroll
        for (int i = 0; i < KVOL; i++) {
            float v = p[i];
            s = fmaf(v, v, s);
        }
        g_bias[n] = 0.5f * s;
    }
}

// ---------------------------------------------------------------------------
// Kernel 2: fused distance-GEMM + top-8 selection.
// 1 thread = 1 spatial position. x-window (75 vals, zero padded to 76) lives
// in registers as 38 packed f32x2 pairs. Patch chunk (negated) staged in smem,
// rows padded to 76 floats so every pair is an aligned LDS.64 broadcast.
// ---------------------------------------------------------------------------
__global__ void __launch_bounds__(256, 2)
dist_topk_kernel(const float* __restrict__ x, const float* __restrict__ patches) {
    __shared__ float sp[NP * 76]; // negated patches, padded rows
    __shared__ float sb[NP];      // bias slice

    int pos = blockIdx.x * 256 + threadIdx.x;
    int w = pos & 63;
    int h = (pos >> 6) & 63;
    int b = pos >> 12;

    // ---- load x window (zero-padded) ----
    float xv[76];
#pragma unroll
    for (int c = 0; c < CC; c++) {
#pragma unroll
        for (int kh = 0; kh < 5; kh++) {
            int hy = h + kh - 2;
            bool rok = (hy >= 0) && (hy < HW);
#pragma unroll
            for (int kw = 0; kw < 5; kw++) {
                int wx = w + kw - 2;
                float v = 0.f;
                if (rok && wx >= 0 && wx < HW)
                    v = x[((b * CC + c) * HW + hy) * HW + wx];
                xv[(c * 5 + kh) * 5 + kw] = v;
            }
        }
    }
    xv[75] = 0.f;

    // pack into 38 x 64-bit pairs (register-resident)
    unsigned long long xp[38];
#pragma unroll
    for (int j = 0; j < 38; j++) {
        asm("mov.b64 %0, {%1,%2};" : "=l"(xp[j]) : "f"(xv[2 * j]), "f"(xv[2 * j + 1]));
    }

    // top-8 (sorted ascending)
    float bestd[KNN];
    int besti[KNN];
#pragma unroll
    for (int j = 0; j < KNN; j++) { bestd[j] = 3.0e38f; besti[j] = 0; }

    for (int ch = 0; ch < NCHUNK; ch++) {
        __syncthreads();
        // stage negated patch chunk
        const float* pg = patches + ch * NP * KVOL;
        for (int i = threadIdx.x; i < NP * KVOL; i += 256) {
            int n = i / KVOL;
            int r = i - n * KVOL;
            sp[n * 76 + r] = -pg[i];
        }
        for (int i = threadIdx.x; i < NP; i += 256) {
            sp[i * 76 + 75] = 0.f;
            sb[i] = g_bias[ch * NP + i];
        }
        __syncthreads();

#pragma unroll 2
        for (int n = 0; n < NP; n++) {
            const unsigned long long* pr =
                reinterpret_cast<const unsigned long long*>(sp + n * 76);
            unsigned long long acc;
            float blo = sb[n];
            asm("mov.b64 %0, {%1,%2};" : "=l"(acc) : "f"(blo), "f"(0.f));
#pragma unroll
            for (int j = 0; j < 38; j++) {
                asm("fma.rn.f32x2 %0, %1, %2, %0;"
                    : "+l"(acc)
                    : "l"(pr[j]), "l"(xp[j]));
            }
            float lo, hi;
            asm("mov.b64 {%0,%1}, %2;" : "=f"(lo), "=f"(hi) : "l"(acc));
            float dist = lo + hi;

            if (dist < bestd[KNN - 1]) {
                // predicated sorted insertion (compare-swap ladder)
                float cand = dist;
                int ci = ch * NP + n;
#pragma unroll
                for (int j = KNN - 1; j >= 1; --j) {
                    float od = bestd[j - 1];
                    int oi = besti[j - 1];
                    bool cl = cand < od;
                    bestd[j] = cl ? od : cand;
                    besti[j] = cl ? oi : ci;
                    cand = cl ? cand : od;
                    ci = cl ? ci : oi;
                }
                bestd[0] = cand;
                besti[0] = ci;
            }
        }
    }

    int* dst = g_topk + pos * KNN;
#pragma unroll
    for (int j = 0; j < KNN; j++) dst[j] = besti[j];
}

// ---------------------------------------------------------------------------
// Kernel 3: gather + mean with coalesced reads and writes via smem transpose.
// block = (b,h, 32-wide w tile). Warp r handles one position: float4-coalesced
// reads of 8 value rows; smem transpose; coalesced NCHW writes.
// ---------------------------------------------------------------------------
__global__ void __launch_bounds__(256)
gather_kernel(const float* __restrict__ values, float* __restrict__ out) {
    __shared__ float ssum[32][133]; // pad 133: stride mod 32 = 5 -> conflict-free reads

    int bh = blockIdx.x;      // b*64 + h
    int wt = blockIdx.y;      // 0..1
    int b = bh >> 6;
    int h = bh & 63;
    int w0 = wt * 32;

    int warp = threadIdx.x >> 5;
    int lane = threadIdx.x & 31;
    const float4* v4 = reinterpret_cast<const float4*>(values);

#pragma unroll
    for (int r = 0; r < 4; r++) {
        int pl = warp + r * 8; // local position 0..31
        int pos = (bh * HW) + w0 + pl;
        const int* ip = g_topk + pos * KNN;
        float4 a = make_float4(0.f, 0.f, 0.f, 0.f);
#pragma unroll
        for (int k = 0; k < KNN; k++) {
            int idx = ip[k]; // uniform across warp
            float4 v = v4[idx * (DD / 4) + lane];
            a.x += v.x; a.y += v.y; a.z += v.z; a.w += v.w;
        }
        ssum[pl][lane * 4 + 0] = a.x * 0.125f;
        ssum[pl][lane * 4 + 1] = a.y * 0.125f;
        ssum[pl][lane * 4 + 2] = a.z * 0.125f;
        ssum[pl][lane * 4 + 3] = a.w * 0.125f;
    }
    __syncthreads();

    int wl = threadIdx.x & 31;
    int d0 = threadIdx.x >> 5; // 0..7
#pragma unroll
    for (int d = d0; d < DD; d += 8) {
        out[((b * DD + d) * HW + h) * HW + w0 + wl] = ssum[wl][d];
    }
}

// ---------------------------------------------------------------------------
extern "C" void kernel_launch(void* const* d_in, const int* in_sizes, int n_in,
                              void* d_out, int out_size) {
    const float* x = (const float*)d_in[0];       // (32,3,64,64)
    const float* patches = (const float*)d_in[1]; // (2048,3,5,5)
    const float* values = (const float*)d_in[2];  // (2048,128)
    float* out = (float*)d_out;                   // (32,128,64,64)

    bias_kernel<<<(NN + 255) / 256, 256>>>(patches);
    dist_topk_kernel<<<NPOS / 256, 256>>>(x, patches);
    gather_kernel<<<dim3(BB * HW, 2), 256>>>(values, out);
}